// round 11
// baseline (speedup 1.0000x reference)
#include <cuda_runtime.h>
#include <cuda_fp16.h>
#include <stdint.h>

// ---------------- Problem constants (fixed dataset) ----------------
#define NMAX 100000
#define EMAX 1600000
#define DIM_IN  512
#define DIM_HID 128
#define DIM_OUT 64

#define SCAN_BLK 1024

// ---------------- Device scratch (no allocations allowed) ----------------
__device__ float g_bufA[(size_t)NMAX * DIM_HID];   // fp16 payloads
__device__ float g_bufB[(size_t)NMAX * DIM_HID];
__device__ int   g_deg[NMAX];
__device__ int   g_cnt[NMAX];
__device__ int   g_rowptr[NMAX + 1];
__device__ int   g_blksum[128];
__device__ int2  g_epack[EMAX];                    // (col, val bits) per CSR slot

// ---------------- helpers ----------------
__device__ __forceinline__ uint32_t smem_u32(const void* p) {
    uint32_t a;
    asm("{ .reg .u64 t; cvta.to.shared.u64 t, %1; cvt.u32.u64 %0, t; }" : "=r"(a) : "l"(p));
    return a;
}
__device__ __forceinline__ uint32_t sw128(uint32_t b) { return b ^ ((b >> 3) & 0x70); }

__device__ __forceinline__ void ldsm_x4(uint32_t* r, uint32_t addr) {
    asm volatile("ldmatrix.sync.aligned.m8n8.x4.shared.b16 {%0,%1,%2,%3}, [%4];"
                 : "=r"(r[0]), "=r"(r[1]), "=r"(r[2]), "=r"(r[3]) : "r"(addr));
}
__device__ __forceinline__ void mma16816(float* d, const uint32_t* a, const uint32_t* b) {
    asm volatile(
        "mma.sync.aligned.m16n8k16.row.col.f32.f16.f16.f32 "
        "{%0,%1,%2,%3}, {%4,%5,%6,%7}, {%8,%9}, {%0,%1,%2,%3};"
        : "+f"(d[0]), "+f"(d[1]), "+f"(d[2]), "+f"(d[3])
        : "r"(a[0]), "r"(a[1]), "r"(a[2]), "r"(a[3]), "r"(b[0]), "r"(b[1]));
}

__device__ __forceinline__ uint2 cvt_hi(float4 v) {
    __half2 h01 = __floats2half2_rn(v.x, v.y);
    __half2 h23 = __floats2half2_rn(v.z, v.w);
    return make_uint2(*(uint32_t*)&h01, *(uint32_t*)&h23);
}
__device__ __forceinline__ uint2 cvt_lo(float4 v, uint2 hi) {
    float2 f01 = __half22float2(*(__half2*)&hi.x);
    float2 f23 = __half22float2(*(__half2*)&hi.y);
    __half2 l01 = __floats2half2_rn(v.x - f01.x, v.y - f01.y);
    __half2 l23 = __floats2half2_rn(v.z - f23.x, v.w - f23.y);
    return make_uint2(*(uint32_t*)&l01, *(uint32_t*)&l23);
}

// ---------------- CSR build ----------------
__global__ void zero_counts_kernel(int n) {
    int i = blockIdx.x * blockDim.x + threadIdx.x;
    if (i < n) { g_deg[i] = 0; g_cnt[i] = 0; }
}

__global__ void hist_kernel(const int* __restrict__ rows, int E) {
    int i = blockIdx.x * blockDim.x + threadIdx.x;
    if (i < E) atomicAdd(&g_deg[rows[i]], 1);
}

__global__ void scan_blocks_kernel(int n) {
    __shared__ int warpsums[32];
    int tid = threadIdx.x, lane = tid & 31, wid = tid >> 5;
    int i = blockIdx.x * SCAN_BLK + tid;
    int v = (i < n) ? g_deg[i] : 0;
    int x = v;
    #pragma unroll
    for (int o = 1; o < 32; o <<= 1) {
        int y = __shfl_up_sync(0xffffffffu, x, o);
        if (lane >= o) x += y;
    }
    if (lane == 31) warpsums[wid] = x;
    __syncthreads();
    if (wid == 0) {
        int s = warpsums[lane];
        #pragma unroll
        for (int o = 1; o < 32; o <<= 1) {
            int y = __shfl_up_sync(0xffffffffu, s, o);
            if (lane >= o) s += y;
        }
        warpsums[lane] = s;
    }
    __syncthreads();
    int pref = (wid > 0) ? warpsums[wid - 1] : 0;
    int incl = x + pref;
    if (i < n) g_rowptr[i] = incl - v;
    if (tid == SCAN_BLK - 1) g_blksum[blockIdx.x] = incl;
}

__global__ void scan_partials_kernel(int nb, int n) {
    __shared__ int warpsums[4];
    int tid = threadIdx.x, lane = tid & 31, wid = tid >> 5;
    int v = (tid < nb) ? g_blksum[tid] : 0;
    int x = v;
    #pragma unroll
    for (int o = 1; o < 32; o <<= 1) {
        int y = __shfl_up_sync(0xffffffffu, x, o);
        if (lane >= o) x += y;
    }
    if (lane == 31) warpsums[wid] = x;
    __syncthreads();
    if (tid == 0) {
        int c = 0;
        #pragma unroll
        for (int q = 0; q < 4; q++) { int t = warpsums[q]; warpsums[q] = c; c += t; }
    }
    __syncthreads();
    int incl = x + warpsums[wid];
    if (tid < nb) g_blksum[tid] = incl - v;
    if (tid == nb - 1) g_rowptr[n] = incl;
}

__global__ void scan_add_kernel(int n) {
    int i = blockIdx.x * SCAN_BLK + threadIdx.x;
    if (i < n) g_rowptr[i] += g_blksum[blockIdx.x];
}

__global__ void scatter_kernel(const int* __restrict__ rows,
                               const int* __restrict__ cols,
                               const float* __restrict__ vals, int E) {
    int i = blockIdx.x * blockDim.x + threadIdx.x;
    if (i < E) {
        int r = rows[i];
        int p = g_rowptr[r] + atomicAdd(&g_cnt[r], 1);
        g_epack[p] = make_int2(cols[i], __float_as_int(vals[i]));
    }
}

// ---------------- GEMM0: C = A(fp32)[M,512] * W[BN,512]^T, fp16 out --------
// 2-term fp16 split (Ah*Bh + Ah*Bl), K-chunk 64, SW128, double-buffered.
template <int BM, int BN, int WM, int WN, int K>
__global__ void __launch_bounds__(WM * WN * 32, 2)
mma_gemm0_kernel(const float* __restrict__ A, const float* __restrict__ W,
                 __half* __restrict__ C, int M)
{
    constexpr int THREADS = WM * WN * 32;
    constexpr int NCHUNK  = K / 64;
    constexpr int ASZ = BM * 128;
    constexpr int BSZ = BN * 128;
    constexpr int BUF = ASZ + 2 * BSZ;
    constexpr int ALF = BM * 16 / THREADS;
    constexpr int BL  = BN * 16 / THREADS;
    constexpr int MT  = BM / WM / 16;
    constexpr int NT  = BN / WN / 8;

    extern __shared__ __align__(1024) char smem[];
    const uint32_t sb = smem_u32(smem);

    const int tid = threadIdx.x;
    const int l   = tid & 31;
    const int w   = tid >> 5;
    const int wmBase = (w % WM) * (BM / WM);
    const int wnBase = (w / WM) * (BN / WN);
    const int m0 = blockIdx.x * BM;

    float acc[MT][NT][4];
    #pragma unroll
    for (int i = 0; i < MT; i++)
        #pragma unroll
        for (int j = 0; j < NT; j++)
            #pragma unroll
            for (int q = 0; q < 4; q++) acc[i][j][q] = 0.f;

    uint2 regAh[ALF];
    uint2 regBh[BL], regBl[BL];

    const int arow = l & 15;
    const int acol = (l & 16) ? 16 : 0;
    const int brow = ((l & 16) ? 8 : 0) + (l & 7);
    const int bcol = (l & 8) ? 16 : 0;

    auto loadChunk = [&](int c) {
        const int k0 = c * 64;
        #pragma unroll
        for (int i = 0; i < ALF; i++) {
            int idx = tid + i * THREADS;
            int r = idx >> 4, c4 = (idx & 15) << 2;
            int row = m0 + r; if (row >= M) row = M - 1;
            float4 v = __ldg((const float4*)(A + (size_t)row * K + k0 + c4));
            regAh[i] = cvt_hi(v);
        }
        #pragma unroll
        for (int i = 0; i < BL; i++) {
            int idx = tid + i * THREADS;
            int r = idx >> 4, c4 = (idx & 15) << 2;
            float4 v = __ldg((const float4*)(W + (size_t)r * K + k0 + c4));
            regBh[i] = cvt_hi(v);
            regBl[i] = cvt_lo(v, regBh[i]);
        }
    };

    auto stsChunk = [&](int b) {
        char* aHi = smem + b * BUF;
        char* bHi = aHi + ASZ;
        char* bLo = bHi + BSZ;
        #pragma unroll
        for (int i = 0; i < ALF; i++) {
            int idx = tid + i * THREADS;
            int r = idx >> 4, c4 = (idx & 15) << 2;
            *(uint2*)(aHi + sw128((uint32_t)(r * 128 + c4 * 2))) = regAh[i];
        }
        #pragma unroll
        for (int i = 0; i < BL; i++) {
            int idx = tid + i * THREADS;
            int r = idx >> 4, c4 = (idx & 15) << 2;
            uint32_t off = sw128((uint32_t)(r * 128 + c4 * 2));
            *(uint2*)(bHi + off) = regBh[i];
            *(uint2*)(bLo + off) = regBl[i];
        }
    };

    auto compute = [&](int b) {
        const uint32_t sAhi = sb + b * BUF;
        const uint32_t sBhi = sAhi + ASZ;
        const uint32_t sBlo = sBhi + BSZ;
        #pragma unroll
        for (int kb = 0; kb < 4; kb++) {
            const int kboff = kb * 32;
            uint32_t aH[MT][4];
            #pragma unroll
            for (int mt = 0; mt < MT; mt++) {
                uint32_t rowb = (uint32_t)((wmBase + mt * 16 + arow) * 128);
                ldsm_x4(aH[mt], sAhi + sw128(rowb + kboff + acol));
            }
            uint32_t bH[NT][2], bLo[NT][2];
            #pragma unroll
            for (int nt = 0; nt < NT; nt += 2) {
                uint32_t rowb = (uint32_t)((wnBase + nt * 8 + brow) * 128);
                uint32_t t[4];
                ldsm_x4(t, sBhi + sw128(rowb + kboff + bcol));
                bH[nt][0] = t[0]; bH[nt][1] = t[1];
                bH[nt + 1][0] = t[2]; bH[nt + 1][1] = t[3];
                ldsm_x4(t, sBlo + sw128(rowb + kboff + bcol));
                bLo[nt][0] = t[0]; bLo[nt][1] = t[1];
                bLo[nt + 1][0] = t[2]; bLo[nt + 1][1] = t[3];
            }
            #pragma unroll
            for (int mt = 0; mt < MT; mt++)
                #pragma unroll
                for (int nt = 0; nt < NT; nt++) {
                    mma16816(acc[mt][nt], aH[mt], bH[nt]);
                    mma16816(acc[mt][nt], aH[mt], bLo[nt]);
                }
        }
    };

    loadChunk(0);
    stsChunk(0);
    __syncthreads();

    for (int c = 0; c < NCHUNK; c++) {
        if (c + 1 < NCHUNK) loadChunk(c + 1);
        compute(c & 1);
        if (c + 1 < NCHUNK) {
            __syncthreads();
            stsChunk((c + 1) & 1);
            __syncthreads();
        }
    }

    #pragma unroll
    for (int mt = 0; mt < MT; mt++) {
        int m = m0 + wmBase + mt * 16 + (l >> 2);
        #pragma unroll
        for (int nt = 0; nt < NT; nt++) {
            int nn = wnBase + nt * 8 + ((l & 3) << 1);
            if (m < M)
                *(__half2*)(C + (size_t)m * BN + nn) =
                    __floats2half2_rn(acc[mt][nt][0], acc[mt][nt][1]);
            if (m + 8 < M)
                *(__half2*)(C + (size_t)(m + 8) * BN + nn) =
                    __floats2half2_rn(acc[mt][nt][2], acc[mt][nt][3]);
        }
    }
}

// ---------------- Fused SpMM(relu) + GEMM ----------------------------------
// h = relu(spmm(Hprev));  C = h @ W^T   (all fp16 payloads, fp32 accum)
// One CTA = 128 output rows. Phase 0: W(fp32[BN,128]) -> smem hi/lo fp16.
// Phase 1: warp-per-row SpMM over Hprev (128-wide fp16 gather), result
// written directly into the GEMM A smem tile (SW128, 2 chunks of 64 cols).
// Phase 2: 2-term fp16 mma over K=128.
template <int BN, int WM, int WN>
__global__ void __launch_bounds__(256, 2)
fused_spmm_gemm(const __half* __restrict__ Hprev, const float* __restrict__ W,
                __half* __restrict__ C, int M)
{
    constexpr int THREADS = 256;
    constexpr int ACH = 128 * 128;      // bytes per A chunk plane (16 KB)
    constexpr int WCH = BN * 128;       // bytes per W chunk per plane
    constexpr int WH_OFF = 2 * ACH;
    constexpr int WL_OFF = WH_OFF + 2 * WCH;
    constexpr int MT = 128 / WM / 16;
    constexpr int NT = BN / WN / 8;
    constexpr int WLOADS = BN * 32 / THREADS;   // float4 loads of W per thread

    extern __shared__ __align__(1024) char smem[];
    const uint32_t sb = smem_u32(smem);

    const int tid = threadIdx.x;
    const int l   = tid & 31;
    const int w   = tid >> 5;
    const int m0  = blockIdx.x * 128;

    // Phase 0: W -> smem hi/lo (chunked 64-col SW128 planes)
    #pragma unroll
    for (int i = 0; i < WLOADS; i++) {
        int idx = tid + i * THREADS;
        int r = idx >> 5, c4 = (idx & 31) << 2;    // 32 float4 per 128-col row
        float4 v = __ldg((const float4*)(W + (size_t)r * 128 + c4));
        uint2 hi = cvt_hi(v);
        uint2 lo = cvt_lo(v, hi);
        int chunk = c4 >> 6;
        uint32_t off = sw128((uint32_t)(r * 128 + (c4 & 63) * 2));
        *(uint2*)(smem + WH_OFF + chunk * WCH + off) = hi;
        *(uint2*)(smem + WL_OFF + chunk * WCH + off) = lo;
    }

    // Phase 1: SpMM for this CTA's 128 rows (warp-per-row, unroll 4)
    const int achunk = l >> 4;
    const uint32_t aoff_lane = (uint32_t)((l & 15) * 8);
    #pragma unroll 1
    for (int rr = 0; rr < 16; rr++) {
        int rlocal = w * 16 + rr;
        int row = m0 + rlocal;
        int s = 0, e = 0;
        if (row < M) { s = g_rowptr[row]; e = g_rowptr[row + 1]; }
        float4 acc = make_float4(0.f, 0.f, 0.f, 0.f);
        int i = s;
        for (; i + 4 <= e; i += 4) {
            int2 p0 = g_epack[i],     p1 = g_epack[i + 1];
            int2 p2 = g_epack[i + 2], p3 = g_epack[i + 3];
            uint2 r0 = __ldg((const uint2*)(Hprev + (size_t)p0.x * 128) + l);
            uint2 r1 = __ldg((const uint2*)(Hprev + (size_t)p1.x * 128) + l);
            uint2 r2 = __ldg((const uint2*)(Hprev + (size_t)p2.x * 128) + l);
            uint2 r3 = __ldg((const uint2*)(Hprev + (size_t)p3.x * 128) + l);
            float v0 = __int_as_float(p0.y), v1 = __int_as_float(p1.y);
            float v2 = __int_as_float(p2.y), v3 = __int_as_float(p3.y);
            float2 a01 = __half22float2(*(__half2*)&r0.x);
            float2 a23 = __half22float2(*(__half2*)&r0.y);
            acc.x += v0 * a01.x; acc.y += v0 * a01.y;
            acc.z += v0 * a23.x; acc.w += v0 * a23.y;
            a01 = __half22float2(*(__half2*)&r1.x);
            a23 = __half22float2(*(__half2*)&r1.y);
            acc.x += v1 * a01.x; acc.y += v1 * a01.y;
            acc.z += v1 * a23.x; acc.w += v1 * a23.y;
            a01 = __half22float2(*(__half2*)&r2.x);
            a23 = __half22float2(*(__half2*)&r2.y);
            acc.x += v2 * a01.x; acc.y += v2 * a01.y;
            acc.z += v2 * a23.x; acc.w += v2 * a23.y;
            a01 = __half22float2(*(__half2*)&r3.x);
            a23 = __half22float2(*(__half2*)&r3.y);
            acc.x += v3 * a01.x; acc.y += v3 * a01.y;
            acc.z += v3 * a23.x; acc.w += v3 * a23.y;
        }
        for (; i < e; i++) {
            int2 p = g_epack[i];
            float v = __int_as_float(p.y);
            uint2 r0 = __ldg((const uint2*)(Hprev + (size_t)p.x * 128) + l);
            float2 a01 = __half22float2(*(__half2*)&r0.x);
            float2 a23 = __half22float2(*(__half2*)&r0.y);
            acc.x += v * a01.x; acc.y += v * a01.y;
            acc.z += v * a23.x; acc.w += v * a23.y;
        }
        // relu + pack fp16 -> GEMM A tile
        acc.x = fmaxf(acc.x, 0.f); acc.y = fmaxf(acc.y, 0.f);
        acc.z = fmaxf(acc.z, 0.f); acc.w = fmaxf(acc.w, 0.f);
        __half2 o01 = __floats2half2_rn(acc.x, acc.y);
        __half2 o23 = __floats2half2_rn(acc.z, acc.w);
        uint32_t off = sw128((uint32_t)(rlocal * 128) + aoff_lane);
        *(uint2*)(smem + achunk * ACH + off) =
            make_uint2(*(uint32_t*)&o01, *(uint32_t*)&o23);
    }
    __syncthreads();

    // Phase 2: GEMM from smem
    const int wmBase = (w % WM) * (128 / WM);
    const int wnBase = (w / WM) * (BN / WN);
    const int arow = l & 15;
    const int acol = (l & 16) ? 16 : 0;
    const int brow = ((l & 16) ? 8 : 0) + (l & 7);
    const int bcol = (l & 8) ? 16 : 0;

    float acc2[MT][NT][4];
    #pragma unroll
    for (int i = 0; i < MT; i++)
        #pragma unroll
        for (int j = 0; j < NT; j++)
            #pragma unroll
            for (int q = 0; q < 4; q++) acc2[i][j][q] = 0.f;

    #pragma unroll
    for (int chunk = 0; chunk < 2; chunk++) {
        const uint32_t sA  = sb + chunk * ACH;
        const uint32_t sWh = sb + WH_OFF + chunk * WCH;
        const uint32_t sWl = sb + WL_OFF + chunk * WCH;
        #pragma unroll
        for (int kb = 0; kb < 4; kb++) {
            const int kboff = kb * 32;
            uint32_t aH[MT][4];
            #pragma unroll
            for (int mt = 0; mt < MT; mt++) {
                uint32_t rowb = (uint32_t)((wmBase + mt * 16 + arow) * 128);
                ldsm_x4(aH[mt], sA + sw128(rowb + kboff + acol));
            }
            uint32_t bH[NT][2], bLo[NT][2];
            #pragma unroll
            for (int nt = 0; nt < NT; nt += 2) {
                uint32_t rowb = (uint32_t)((wnBase + nt * 8 + brow) * 128);
                uint32_t t[4];
                ldsm_x4(t, sWh + sw128(rowb + kboff + bcol));
                bH[nt][0] = t[0]; bH[nt][1] = t[1];
                bH[nt + 1][0] = t[2]; bH[nt + 1][1] = t[3];
                ldsm_x4(t, sWl + sw128(rowb + kboff + bcol));
                bLo[nt][0] = t[0]; bLo[nt][1] = t[1];
                bLo[nt + 1][0] = t[2]; bLo[nt + 1][1] = t[3];
            }
            #pragma unroll
            for (int mt = 0; mt < MT; mt++)
                #pragma unroll
                for (int nt = 0; nt < NT; nt++) {
                    mma16816(acc2[mt][nt], aH[mt], bH[nt]);
                    mma16816(acc2[mt][nt], aH[mt], bLo[nt]);
                }
        }
    }

    // epilogue: fp16 out
    #pragma unroll
    for (int mt = 0; mt < MT; mt++) {
        int m = m0 + wmBase + mt * 16 + (l >> 2);
        #pragma unroll
        for (int nt = 0; nt < NT; nt++) {
            int nn = wnBase + nt * 8 + ((l & 3) << 1);
            if (m < M)
                *(__half2*)(C + (size_t)m * BN + nn) =
                    __floats2half2_rn(acc2[mt][nt][0], acc2[mt][nt][1]);
            if (m + 8 < M)
                *(__half2*)(C + (size_t)(m + 8) * BN + nn) =
                    __floats2half2_rn(acc2[mt][nt][2], acc2[mt][nt][3]);
        }
    }
}

// ---------------- Final SpMM (width 64, fp16 gather, fp32 out) -------------
__global__ void spmm_final_kernel(const __half* __restrict__ h,
                                  float* __restrict__ out, int n) {
    int warp = (blockIdx.x * blockDim.x + threadIdx.x) >> 5;
    int lane = threadIdx.x & 31;
    if (warp >= n) return;
    int s = g_rowptr[warp];
    int e = g_rowptr[warp + 1];

    float2 acc = make_float2(0.f, 0.f);
    int i = s;
    for (; i + 2 <= e; i += 2) {
        int2 p0 = g_epack[i];
        int2 p1 = g_epack[i + 1];
        float v0 = __int_as_float(p0.y);
        float v1 = __int_as_float(p1.y);
        uint32_t r0 = __ldg((const uint32_t*)(h + (size_t)p0.x * 64) + lane);
        uint32_t r1 = __ldg((const uint32_t*)(h + (size_t)p1.x * 64) + lane);
        float2 a = __half22float2(*(__half2*)&r0);
        float2 b = __half22float2(*(__half2*)&r1);
        acc.x += v0 * a.x; acc.y += v0 * a.y;
        acc.x += v1 * b.x; acc.y += v1 * b.y;
    }
    if (i < e) {
        int2 p = g_epack[i];
        float v = __int_as_float(p.y);
        uint32_t r0 = __ldg((const uint32_t*)(h + (size_t)p.x * 64) + lane);
        float2 a = __half22float2(*(__half2*)&r0);
        acc.x += v * a.x; acc.y += v * a.y;
    }
    ((float2*)(out + (size_t)warp * 64))[lane] = acc;
}

// ---------------- Launcher ----------------
extern "C" void kernel_launch(void* const* d_in, const int* in_sizes, int n_in,
                              void* d_out, int out_size) {
    const float* x    = (const float*)d_in[0];
    const int*   rows = (const int*)  d_in[1];
    const int*   cols = (const int*)  d_in[2];
    const float* vals = (const float*)d_in[3];
    const float* W0   = (const float*)d_in[4];
    const float* W1   = (const float*)d_in[5];
    const float* W2   = (const float*)d_in[6];
    float* out = (float*)d_out;

    int n = in_sizes[0] / DIM_IN;   // 100000
    int E = in_sizes[1];            // 1600000
    int nb = (n + SCAN_BLK - 1) / SCAN_BLK;

    float* bufA; float* bufB;
    cudaGetSymbolAddress((void**)&bufA, g_bufA);
    cudaGetSymbolAddress((void**)&bufB, g_bufB);
    __half* bufAh = (__half*)bufA;
    __half* bufBh = (__half*)bufB;

    const int smemG0 = 2 * 48 * 1024;                 // 96 KB
    const int smemF1 = 2 * 128 * 128 + 4 * 128 * 128; // 96 KB (BN=128)
    const int smemF2 = 2 * 128 * 128 + 4 * 64 * 128;  // 64 KB (BN=64)
    auto g0 = mma_gemm0_kernel<128, 128, 2, 4, 512>;
    auto f1 = fused_spmm_gemm<128, 2, 4>;
    auto f2 = fused_spmm_gemm<64, 4, 2>;
    cudaFuncSetAttribute(g0, cudaFuncAttributeMaxDynamicSharedMemorySize, smemG0);
    cudaFuncSetAttribute(f1, cudaFuncAttributeMaxDynamicSharedMemorySize, smemF1);
    cudaFuncSetAttribute(f2, cudaFuncAttributeMaxDynamicSharedMemorySize, smemF2);

    // ---- CSR build (multi-block scan) ----
    zero_counts_kernel<<<(n + 255) / 256, 256>>>(n);
    hist_kernel<<<(E + 255) / 256, 256>>>(rows, E);
    scan_blocks_kernel<<<nb, SCAN_BLK>>>(n);
    scan_partials_kernel<<<1, 128>>>(nb, n);
    scan_add_kernel<<<nb, SCAN_BLK>>>(n);
    scatter_kernel<<<(E + 255) / 256, 256>>>(rows, cols, vals, E);

    int gemmGrid = (n + 127) / 128;
    int spmmGrid = (n + 7) / 8;

    // layer 0: x(fp32) @ W0^T -> fp16 h0'
    g0<<<gemmGrid, 256, smemG0>>>(x, W0, bufAh, n);
    // layer 1 fused: h1 = relu(spmm(h0')); h1' = h1 @ W1^T (fp16)
    f1<<<gemmGrid, 256, smemF1>>>(bufAh, W1, bufBh, n);
    // layer 2 fused: h2 = relu(spmm(h1')); h2' = h2 @ W2^T (fp16, width 64)
    f2<<<gemmGrid, 256, smemF2>>>(bufBh, W2, bufAh, n);
    // output: spmm(h2') -> fp32
    spmm_final_kernel<<<spmmGrid, 256>>>(bufAh, out, n);
}

// round 12
// speedup vs baseline: 1.3094x; 1.3094x over previous
#include <cuda_runtime.h>
#include <cuda_fp16.h>
#include <stdint.h>

// ---------------- Problem constants (fixed dataset) ----------------
#define NMAX 100000
#define EMAX 1600000
#define DIM_IN  512
#define DIM_HID 128
#define DIM_OUT 64

#define SCAN_BLK 1024

// ---------------- Device scratch (no allocations allowed) ----------------
__device__ float g_bufA[(size_t)NMAX * DIM_HID];   // gemm outputs (fp16 stored)
__device__ float g_bufB[(size_t)NMAX * DIM_HID];   // spmm outputs (fp16 stored)
__device__ int   g_deg[NMAX];
__device__ int   g_cnt[NMAX];
__device__ int   g_rowptr[NMAX + 1];
__device__ int   g_blksum[128];
__device__ int2  g_epack[EMAX];                    // (col, val bits) per CSR slot

// ---------------- helpers ----------------
__device__ __forceinline__ uint32_t smem_u32(const void* p) {
    uint32_t a;
    asm("{ .reg .u64 t; cvta.to.shared.u64 t, %1; cvt.u32.u64 %0, t; }" : "=r"(a) : "l"(p));
    return a;
}
__device__ __forceinline__ uint32_t sw128(uint32_t b) { return b ^ ((b >> 3) & 0x70); }

__device__ __forceinline__ void ldsm_x4(uint32_t* r, uint32_t addr) {
    asm volatile("ldmatrix.sync.aligned.m8n8.x4.shared.b16 {%0,%1,%2,%3}, [%4];"
                 : "=r"(r[0]), "=r"(r[1]), "=r"(r[2]), "=r"(r[3]) : "r"(addr));
}
// fp16 MMA, fp32 accumulate
__device__ __forceinline__ void mma16816(float* d, const uint32_t* a, const uint32_t* b) {
    asm volatile(
        "mma.sync.aligned.m16n8k16.row.col.f32.f16.f16.f32 "
        "{%0,%1,%2,%3}, {%4,%5,%6,%7}, {%8,%9}, {%0,%1,%2,%3};"
        : "+f"(d[0]), "+f"(d[1]), "+f"(d[2]), "+f"(d[3])
        : "r"(a[0]), "r"(a[1]), "r"(a[2]), "r"(a[3]), "r"(b[0]), "r"(b[1]));
}

__device__ __forceinline__ uint2 cvt_hi(float4 v) {
    __half2 h01 = __floats2half2_rn(v.x, v.y);
    __half2 h23 = __floats2half2_rn(v.z, v.w);
    return make_uint2(*(uint32_t*)&h01, *(uint32_t*)&h23);
}
__device__ __forceinline__ uint2 cvt_lo(float4 v, uint2 hi) {
    float2 f01 = __half22float2(*(__half2*)&hi.x);
    float2 f23 = __half22float2(*(__half2*)&hi.y);
    __half2 l01 = __floats2half2_rn(v.x - f01.x, v.y - f01.y);
    __half2 l23 = __floats2half2_rn(v.z - f23.x, v.w - f23.y);
    return make_uint2(*(uint32_t*)&l01, *(uint32_t*)&l23);
}

// ---------------- CSR build ----------------
__global__ void zero_counts_kernel(int n) {
    int i = blockIdx.x * blockDim.x + threadIdx.x;
    if (i < n) { g_deg[i] = 0; g_cnt[i] = 0; }
}

__global__ void hist_kernel(const int* __restrict__ rows, int E) {
    int i = blockIdx.x * blockDim.x + threadIdx.x;
    if (i < E) atomicAdd(&g_deg[rows[i]], 1);
}

__global__ void scan_blocks_kernel(int n) {
    __shared__ int warpsums[32];
    int tid = threadIdx.x, lane = tid & 31, wid = tid >> 5;
    int i = blockIdx.x * SCAN_BLK + tid;
    int v = (i < n) ? g_deg[i] : 0;
    int x = v;
    #pragma unroll
    for (int o = 1; o < 32; o <<= 1) {
        int y = __shfl_up_sync(0xffffffffu, x, o);
        if (lane >= o) x += y;
    }
    if (lane == 31) warpsums[wid] = x;
    __syncthreads();
    if (wid == 0) {
        int s = warpsums[lane];
        #pragma unroll
        for (int o = 1; o < 32; o <<= 1) {
            int y = __shfl_up_sync(0xffffffffu, s, o);
            if (lane >= o) s += y;
        }
        warpsums[lane] = s;
    }
    __syncthreads();
    int pref = (wid > 0) ? warpsums[wid - 1] : 0;
    int incl = x + pref;
    if (i < n) g_rowptr[i] = incl - v;
    if (tid == SCAN_BLK - 1) g_blksum[blockIdx.x] = incl;
}

__global__ void scan_partials_kernel(int nb, int n) {
    __shared__ int warpsums[4];
    int tid = threadIdx.x, lane = tid & 31, wid = tid >> 5;
    int v = (tid < nb) ? g_blksum[tid] : 0;
    int x = v;
    #pragma unroll
    for (int o = 1; o < 32; o <<= 1) {
        int y = __shfl_up_sync(0xffffffffu, x, o);
        if (lane >= o) x += y;
    }
    if (lane == 31) warpsums[wid] = x;
    __syncthreads();
    if (tid == 0) {
        int c = 0;
        #pragma unroll
        for (int q = 0; q < 4; q++) { int t = warpsums[q]; warpsums[q] = c; c += t; }
    }
    __syncthreads();
    int incl = x + warpsums[wid];
    if (tid < nb) g_blksum[tid] = incl - v;
    if (tid == nb - 1) g_rowptr[n] = incl;
}

__global__ void scan_add_kernel(int n) {
    int i = blockIdx.x * SCAN_BLK + threadIdx.x;
    if (i < n) g_rowptr[i] += g_blksum[blockIdx.x];
}

__global__ void scatter_kernel(const int* __restrict__ rows,
                               const int* __restrict__ cols,
                               const float* __restrict__ vals, int E) {
    int i = blockIdx.x * blockDim.x + threadIdx.x;
    if (i < E) {
        int r = rows[i];
        int p = g_rowptr[r] + atomicAdd(&g_cnt[r], 1);
        g_epack[p] = make_int2(cols[i], __float_as_int(vals[i]));
    }
}

// ---------------- Tensor-core GEMM via fp16 mma.sync ----------------
// C[M,BN] = A[M,K] * W[BN,K]^T, 2-term fp16 split: D += Ah*Bh + Ah*Bl.
// AHALF: A already fp16 (Ah == A exactly; smem fill is a straight copy).
// K-chunk = 64 -> 128B fp16 rows, SW128 swizzle, double-buffered. fp16 out.
template <int BM, int BN, int WM, int WN, int K, bool AHALF>
__global__ void __launch_bounds__(WM * WN * 32, 2)
mma_gemm_kernel(const void* __restrict__ Av, const float* __restrict__ W,
                __half* __restrict__ C, int M)
{
    constexpr int THREADS = WM * WN * 32;
    constexpr int NCHUNK  = K / 64;
    constexpr int ASZ = BM * 128;                // A plane bytes (hi only)
    constexpr int BSZ = BN * 128;                // per B plane
    constexpr int BUF = ASZ + 2 * BSZ;
    constexpr int ALF = BM * 16 / THREADS;       // float4 loads (fp32 A)
    constexpr int ALH = BM * 8 / THREADS;        // uint4 loads (fp16 A)
    constexpr int BL  = BN * 16 / THREADS;       // float4 loads (W)
    constexpr int MT  = BM / WM / 16;
    constexpr int NT  = BN / WN / 8;

    extern __shared__ __align__(1024) char smem[];
    const uint32_t sb = smem_u32(smem);

    const int tid = threadIdx.x;
    const int l   = tid & 31;
    const int w   = tid >> 5;
    const int wmBase = (w % WM) * (BM / WM);
    const int wnBase = (w / WM) * (BN / WN);
    const int m0 = blockIdx.x * BM;

    const float*  Af = (const float*)Av;
    const __half* Ah = (const __half*)Av;

    float acc[MT][NT][4];
    #pragma unroll
    for (int i = 0; i < MT; i++)
        #pragma unroll
        for (int j = 0; j < NT; j++)
            #pragma unroll
            for (int q = 0; q < 4; q++) acc[i][j][q] = 0.f;

    uint2 regAh[AHALF ? 1 : ALF];
    uint4 regAp[AHALF ? ALH : 1];
    uint2 regBh[BL], regBl[BL];

    const int arow = l & 15;
    const int acol = (l & 16) ? 16 : 0;
    const int brow = ((l & 16) ? 8 : 0) + (l & 7);
    const int bcol = (l & 8) ? 16 : 0;

    auto loadChunk = [&](int c) {
        const int k0 = c * 64;
        if constexpr (AHALF) {
            #pragma unroll
            for (int i = 0; i < ALH; i++) {
                int idx = tid + i * THREADS;
                int r = idx >> 3, u = idx & 7;           // 8 uint4 per 128B row
                int row = m0 + r; if (row >= M) row = M - 1;
                regAp[i] = __ldg((const uint4*)(Ah + (size_t)row * K + k0) + u);
            }
        } else {
            #pragma unroll
            for (int i = 0; i < ALF; i++) {
                int idx = tid + i * THREADS;
                int r = idx >> 4, c4 = (idx & 15) << 2;
                int row = m0 + r; if (row >= M) row = M - 1;
                float4 v = __ldg((const float4*)(Af + (size_t)row * K + k0 + c4));
                regAh[i] = cvt_hi(v);
            }
        }
        #pragma unroll
        for (int i = 0; i < BL; i++) {
            int idx = tid + i * THREADS;
            int r = idx >> 4, c4 = (idx & 15) << 2;
            float4 v = __ldg((const float4*)(W + (size_t)r * K + k0 + c4));
            regBh[i] = cvt_hi(v);
            regBl[i] = cvt_lo(v, regBh[i]);
        }
    };

    auto stsChunk = [&](int b) {
        char* base = smem + b * BUF;
        char* aHi  = base;
        char* bHi  = base + ASZ;
        char* bLo  = bHi + BSZ;
        if constexpr (AHALF) {
            #pragma unroll
            for (int i = 0; i < ALH; i++) {
                int idx = tid + i * THREADS;
                int r = idx >> 3, u = idx & 7;
                *(uint4*)(aHi + sw128((uint32_t)(r * 128 + u * 16))) = regAp[i];
            }
        } else {
            #pragma unroll
            for (int i = 0; i < ALF; i++) {
                int idx = tid + i * THREADS;
                int r = idx >> 4, c4 = (idx & 15) << 2;
                *(uint2*)(aHi + sw128((uint32_t)(r * 128 + c4 * 2))) = regAh[i];
            }
        }
        #pragma unroll
        for (int i = 0; i < BL; i++) {
            int idx = tid + i * THREADS;
            int r = idx >> 4, c4 = (idx & 15) << 2;
            uint32_t off = sw128((uint32_t)(r * 128 + c4 * 2));
            *(uint2*)(bHi + off) = regBh[i];
            *(uint2*)(bLo + off) = regBl[i];
        }
    };

    auto compute = [&](int b) {
        const uint32_t sAhi = sb + b * BUF;
        const uint32_t sBhi = sAhi + ASZ;
        const uint32_t sBlo = sBhi + BSZ;
        #pragma unroll
        for (int kb = 0; kb < 4; kb++) {
            const int kboff = kb * 32;
            uint32_t aH[MT][4];
            #pragma unroll
            for (int mt = 0; mt < MT; mt++) {
                uint32_t rowb = (uint32_t)((wmBase + mt * 16 + arow) * 128);
                ldsm_x4(aH[mt], sAhi + sw128(rowb + kboff + acol));
            }
            uint32_t bH[NT][2], bLo[NT][2];
            #pragma unroll
            for (int nt = 0; nt < NT; nt += 2) {
                uint32_t rowb = (uint32_t)((wnBase + nt * 8 + brow) * 128);
                uint32_t t[4];
                ldsm_x4(t, sBhi + sw128(rowb + kboff + bcol));
                bH[nt][0] = t[0]; bH[nt][1] = t[1];
                bH[nt + 1][0] = t[2]; bH[nt + 1][1] = t[3];
                ldsm_x4(t, sBlo + sw128(rowb + kboff + bcol));
                bLo[nt][0] = t[0]; bLo[nt][1] = t[1];
                bLo[nt + 1][0] = t[2]; bLo[nt + 1][1] = t[3];
            }
            #pragma unroll
            for (int mt = 0; mt < MT; mt++)
                #pragma unroll
                for (int nt = 0; nt < NT; nt++) {
                    mma16816(acc[mt][nt], aH[mt], bH[nt]);
                    mma16816(acc[mt][nt], aH[mt], bLo[nt]);
                }
        }
    };

    loadChunk(0);
    stsChunk(0);
    __syncthreads();

    for (int c = 0; c < NCHUNK; c++) {
        if (c + 1 < NCHUNK) loadChunk(c + 1);
        compute(c & 1);
        if (c + 1 < NCHUNK) {
            __syncthreads();
            stsChunk((c + 1) & 1);
            __syncthreads();
        }
    }

    #pragma unroll
    for (int mt = 0; mt < MT; mt++) {
        int m = m0 + wmBase + mt * 16 + (l >> 2);
        #pragma unroll
        for (int nt = 0; nt < NT; nt++) {
            int nn = wnBase + nt * 8 + ((l & 3) << 1);
            if (m < M)
                *(__half2*)(C + (size_t)m * BN + nn) =
                    __floats2half2_rn(acc[mt][nt][0], acc[mt][nt][1]);
            if (m + 8 < M)
                *(__half2*)(C + (size_t)(m + 8) * BN + nn) =
                    __floats2half2_rn(acc[mt][nt][2], acc[mt][nt][3]);
        }
    }
}

// ---------------- SpMM (CSR, warp per row, fp16 gather, 4x unroll) ---------
// h fp16, accumulate fp32. OUTHALF: store fp16, else fp32.
template <int WIDTH, bool RELU, bool OUTHALF>
__global__ void spmm_kernel(const __half* __restrict__ h,
                            void* __restrict__ outv, int n) {
    int warp = (blockIdx.x * blockDim.x + threadIdx.x) >> 5;
    int lane = threadIdx.x & 31;
    if (warp >= n) return;
    int s = g_rowptr[warp];
    int e = g_rowptr[warp + 1];

    if (WIDTH == 128) {
        float4 acc = make_float4(0.f, 0.f, 0.f, 0.f);
        int i = s;
        for (; i + 4 <= e; i += 4) {
            int2 p0 = g_epack[i],     p1 = g_epack[i + 1];
            int2 p2 = g_epack[i + 2], p3 = g_epack[i + 3];
            uint2 r0 = __ldg((const uint2*)(h + (size_t)p0.x * 128) + lane);
            uint2 r1 = __ldg((const uint2*)(h + (size_t)p1.x * 128) + lane);
            uint2 r2 = __ldg((const uint2*)(h + (size_t)p2.x * 128) + lane);
            uint2 r3 = __ldg((const uint2*)(h + (size_t)p3.x * 128) + lane);
            float v0 = __int_as_float(p0.y), v1 = __int_as_float(p1.y);
            float v2 = __int_as_float(p2.y), v3 = __int_as_float(p3.y);
            float2 a01 = __half22float2(*(__half2*)&r0.x);
            float2 a23 = __half22float2(*(__half2*)&r0.y);
            acc.x += v0 * a01.x; acc.y += v0 * a01.y;
            acc.z += v0 * a23.x; acc.w += v0 * a23.y;
            a01 = __half22float2(*(__half2*)&r1.x);
            a23 = __half22float2(*(__half2*)&r1.y);
            acc.x += v1 * a01.x; acc.y += v1 * a01.y;
            acc.z += v1 * a23.x; acc.w += v1 * a23.y;
            a01 = __half22float2(*(__half2*)&r2.x);
            a23 = __half22float2(*(__half2*)&r2.y);
            acc.x += v2 * a01.x; acc.y += v2 * a01.y;
            acc.z += v2 * a23.x; acc.w += v2 * a23.y;
            a01 = __half22float2(*(__half2*)&r3.x);
            a23 = __half22float2(*(__half2*)&r3.y);
            acc.x += v3 * a01.x; acc.y += v3 * a01.y;
            acc.z += v3 * a23.x; acc.w += v3 * a23.y;
        }
        for (; i < e; i++) {
            int2 p = g_epack[i];
            float v = __int_as_float(p.y);
            uint2 r0 = __ldg((const uint2*)(h + (size_t)p.x * 128) + lane);
            float2 a01 = __half22float2(*(__half2*)&r0.x);
            float2 a23 = __half22float2(*(__half2*)&r0.y);
            acc.x += v * a01.x; acc.y += v * a01.y;
            acc.z += v * a23.x; acc.w += v * a23.y;
        }
        if (RELU) {
            acc.x = fmaxf(acc.x, 0.f); acc.y = fmaxf(acc.y, 0.f);
            acc.z = fmaxf(acc.z, 0.f); acc.w = fmaxf(acc.w, 0.f);
        }
        if constexpr (OUTHALF) {
            __half2 o01 = __floats2half2_rn(acc.x, acc.y);
            __half2 o23 = __floats2half2_rn(acc.z, acc.w);
            ((uint2*)((__half*)outv + (size_t)warp * 128))[lane] =
                make_uint2(*(uint32_t*)&o01, *(uint32_t*)&o23);
        } else {
            ((float4*)((float*)outv + (size_t)warp * 128))[lane] = acc;
        }
    } else {  // WIDTH == 64
        float2 acc = make_float2(0.f, 0.f);
        int i = s;
        for (; i + 4 <= e; i += 4) {
            int2 p0 = g_epack[i],     p1 = g_epack[i + 1];
            int2 p2 = g_epack[i + 2], p3 = g_epack[i + 3];
            uint32_t r0 = __ldg((const uint32_t*)(h + (size_t)p0.x * 64) + lane);
            uint32_t r1 = __ldg((const uint32_t*)(h + (size_t)p1.x * 64) + lane);
            uint32_t r2 = __ldg((const uint32_t*)(h + (size_t)p2.x * 64) + lane);
            uint32_t r3 = __ldg((const uint32_t*)(h + (size_t)p3.x * 64) + lane);
            float v0 = __int_as_float(p0.y), v1 = __int_as_float(p1.y);
            float v2 = __int_as_float(p2.y), v3 = __int_as_float(p3.y);
            float2 a = __half22float2(*(__half2*)&r0);
            acc.x += v0 * a.x; acc.y += v0 * a.y;
            a = __half22float2(*(__half2*)&r1);
            acc.x += v1 * a.x; acc.y += v1 * a.y;
            a = __half22float2(*(__half2*)&r2);
            acc.x += v2 * a.x; acc.y += v2 * a.y;
            a = __half22float2(*(__half2*)&r3);
            acc.x += v3 * a.x; acc.y += v3 * a.y;
        }
        for (; i < e; i++) {
            int2 p = g_epack[i];
            float v = __int_as_float(p.y);
            uint32_t r0 = __ldg((const uint32_t*)(h + (size_t)p.x * 64) + lane);
            float2 a = __half22float2(*(__half2*)&r0);
            acc.x += v * a.x; acc.y += v * a.y;
        }
        if (RELU) { acc.x = fmaxf(acc.x, 0.f); acc.y = fmaxf(acc.y, 0.f); }
        ((float2*)((float*)outv + (size_t)warp * 64))[lane] = acc;
    }
}

// ---------------- Launcher ----------------
extern "C" void kernel_launch(void* const* d_in, const int* in_sizes, int n_in,
                              void* d_out, int out_size) {
    const float* x    = (const float*)d_in[0];
    const int*   rows = (const int*)  d_in[1];
    const int*   cols = (const int*)  d_in[2];
    const float* vals = (const float*)d_in[3];
    const float* W0   = (const float*)d_in[4];
    const float* W1   = (const float*)d_in[5];
    const float* W2   = (const float*)d_in[6];
    float* out = (float*)d_out;

    int n = in_sizes[0] / DIM_IN;   // 100000
    int E = in_sizes[1];            // 1600000
    int nb = (n + SCAN_BLK - 1) / SCAN_BLK;

    float* bufA; float* bufB;
    cudaGetSymbolAddress((void**)&bufA, g_bufA);
    cudaGetSymbolAddress((void**)&bufB, g_bufB);
    __half* bufAh = (__half*)bufA;
    __half* bufBh = (__half*)bufB;

    // smem per stage: ASZ 16K + 2*BSZ (BN=128: 32K -> 48K; BN=64: 16K -> 32K)
    const int smemG0 = 2 * 48 * 1024;
    const int smemG2 = 2 * 32 * 1024;
    cudaFuncSetAttribute(mma_gemm_kernel<128, 128, 2, 4, 512, false>,
                         cudaFuncAttributeMaxDynamicSharedMemorySize, smemG0);
    cudaFuncSetAttribute(mma_gemm_kernel<128, 128, 2, 4, 128, true>,
                         cudaFuncAttributeMaxDynamicSharedMemorySize, smemG0);
    cudaFuncSetAttribute(mma_gemm_kernel<128, 64, 4, 2, 128, true>,
                         cudaFuncAttributeMaxDynamicSharedMemorySize, smemG2);

    // ---- CSR build (multi-block scan) ----
    zero_counts_kernel<<<(n + 255) / 256, 256>>>(n);
    hist_kernel<<<(E + 255) / 256, 256>>>(rows, E);
    scan_blocks_kernel<<<nb, SCAN_BLK>>>(n);
    scan_partials_kernel<<<1, 128>>>(nb, n);
    scan_add_kernel<<<nb, SCAN_BLK>>>(n);
    scatter_kernel<<<(E + 255) / 256, 256>>>(rows, cols, vals, E);

    int gemmGrid = (n + 127) / 128;
    int spmmGrid = (n + 7) / 8;

    // layer 0: x(fp32) @ W0^T -> fp16; spmm fp16->fp16 + relu
    mma_gemm_kernel<128, 128, 2, 4, 512, false><<<gemmGrid, 256, smemG0>>>(x, W0, bufAh, n);
    spmm_kernel<128, true, true><<<spmmGrid, 256>>>(bufAh, bufBh, n);

    // layer 1: h(fp16) @ W1^T -> fp16; spmm fp16->fp16 + relu
    mma_gemm_kernel<128, 128, 2, 4, 128, true><<<gemmGrid, 256, smemG0>>>(bufBh, W1, bufAh, n);
    spmm_kernel<128, true, true><<<spmmGrid, 256>>>(bufAh, bufBh, n);

    // layer 2: h(fp16) @ W2^T -> fp16; spmm fp16->fp32 (no relu)
    mma_gemm_kernel<128, 64, 4, 2, 128, true><<<gemmGrid, 256, smemG2>>>(bufBh, W2, bufAh, n);
    spmm_kernel<64, false, false><<<spmmGrid, 256>>>(bufAh, out, n);
}

// round 13
// speedup vs baseline: 1.3998x; 1.0691x over previous
#include <cuda_runtime.h>
#include <cuda_fp16.h>
#include <stdint.h>

// ---------------- Problem constants (fixed dataset) ----------------
#define NMAX 100000
#define EMAX 1600000
#define DIM_IN  512
#define DIM_HID 128
#define DIM_OUT 64

#define SCAN_BLK 1024

// ---------------- Device scratch (no allocations allowed) ----------------
__device__ float g_bufA[(size_t)NMAX * DIM_HID];   // gemm outputs (fp16 stored)
__device__ float g_bufB[(size_t)NMAX * DIM_HID];   // spmm outputs (fp16 stored)
__device__ int   g_deg[NMAX];
__device__ int   g_rowptr[NMAX + 1];
__device__ int   g_rowptr2[NMAX];                  // mutable copy for scatter
__device__ int   g_blksum[128];
__device__ int2  g_epack[EMAX];                    // (col, val bits) per CSR slot

// ---------------- helpers ----------------
__device__ __forceinline__ uint32_t smem_u32(const void* p) {
    uint32_t a;
    asm("{ .reg .u64 t; cvta.to.shared.u64 t, %1; cvt.u32.u64 %0, t; }" : "=r"(a) : "l"(p));
    return a;
}
__device__ __forceinline__ uint32_t sw128(uint32_t b) { return b ^ ((b >> 3) & 0x70); }

__device__ __forceinline__ void ldsm_x4(uint32_t* r, uint32_t addr) {
    asm volatile("ldmatrix.sync.aligned.m8n8.x4.shared.b16 {%0,%1,%2,%3}, [%4];"
                 : "=r"(r[0]), "=r"(r[1]), "=r"(r[2]), "=r"(r[3]) : "r"(addr));
}
// fp16 MMA, fp32 accumulate
__device__ __forceinline__ void mma16816(float* d, const uint32_t* a, const uint32_t* b) {
    asm volatile(
        "mma.sync.aligned.m16n8k16.row.col.f32.f16.f16.f32 "
        "{%0,%1,%2,%3}, {%4,%5,%6,%7}, {%8,%9}, {%0,%1,%2,%3};"
        : "+f"(d[0]), "+f"(d[1]), "+f"(d[2]), "+f"(d[3])
        : "r"(a[0]), "r"(a[1]), "r"(a[2]), "r"(a[3]), "r"(b[0]), "r"(b[1]));
}

__device__ __forceinline__ uint2 cvt_hi(float4 v) {
    __half2 h01 = __floats2half2_rn(v.x, v.y);
    __half2 h23 = __floats2half2_rn(v.z, v.w);
    return make_uint2(*(uint32_t*)&h01, *(uint32_t*)&h23);
}
__device__ __forceinline__ uint2 cvt_lo(float4 v, uint2 hi) {
    float2 f01 = __half22float2(*(__half2*)&hi.x);
    float2 f23 = __half22float2(*(__half2*)&hi.y);
    __half2 l01 = __floats2half2_rn(v.x - f01.x, v.y - f01.y);
    __half2 l23 = __floats2half2_rn(v.z - f23.x, v.w - f23.y);
    return make_uint2(*(uint32_t*)&l01, *(uint32_t*)&l23);
}

// ---------------- CSR build ----------------
__global__ void zero_deg_kernel(int n) {
    int i = blockIdx.x * blockDim.x + threadIdx.x;
    if (i < n) g_deg[i] = 0;
}

__global__ void hist_kernel(const int* __restrict__ rows, int E) {
    int i = blockIdx.x * blockDim.x + threadIdx.x;
    if (i < E) atomicAdd(&g_deg[rows[i]], 1);
}

__global__ void scan_blocks_kernel(int n) {
    __shared__ int warpsums[32];
    int tid = threadIdx.x, lane = tid & 31, wid = tid >> 5;
    int i = blockIdx.x * SCAN_BLK + tid;
    int v = (i < n) ? g_deg[i] : 0;
    int x = v;
    #pragma unroll
    for (int o = 1; o < 32; o <<= 1) {
        int y = __shfl_up_sync(0xffffffffu, x, o);
        if (lane >= o) x += y;
    }
    if (lane == 31) warpsums[wid] = x;
    __syncthreads();
    if (wid == 0) {
        int s = warpsums[lane];
        #pragma unroll
        for (int o = 1; o < 32; o <<= 1) {
            int y = __shfl_up_sync(0xffffffffu, s, o);
            if (lane >= o) s += y;
        }
        warpsums[lane] = s;
    }
    __syncthreads();
    int pref = (wid > 0) ? warpsums[wid - 1] : 0;
    int incl = x + pref;
    if (i < n) g_rowptr[i] = incl - v;
    if (tid == SCAN_BLK - 1) g_blksum[blockIdx.x] = incl;
}

__global__ void scan_partials_kernel(int nb, int n) {
    __shared__ int warpsums[4];
    int tid = threadIdx.x, lane = tid & 31, wid = tid >> 5;
    int v = (tid < nb) ? g_blksum[tid] : 0;
    int x = v;
    #pragma unroll
    for (int o = 1; o < 32; o <<= 1) {
        int y = __shfl_up_sync(0xffffffffu, x, o);
        if (lane >= o) x += y;
    }
    if (lane == 31) warpsums[wid] = x;
    __syncthreads();
    if (tid == 0) {
        int c = 0;
        #pragma unroll
        for (int q = 0; q < 4; q++) { int t = warpsums[q]; warpsums[q] = c; c += t; }
    }
    __syncthreads();
    int incl = x + warpsums[wid];
    if (tid < nb) g_blksum[tid] = incl - v;
    if (tid == nb - 1) g_rowptr[n] = incl;
}

// Adds block offsets AND materializes the mutable scatter cursor copy.
__global__ void scan_add_kernel(int n) {
    int i = blockIdx.x * SCAN_BLK + threadIdx.x;
    if (i < n) {
        int v = g_rowptr[i] + g_blksum[blockIdx.x];
        g_rowptr[i]  = v;
        g_rowptr2[i] = v;
    }
}

// Single atomic per edge: cursor atomicAdd yields the slot directly.
__global__ void scatter_kernel(const int* __restrict__ rows,
                               const int* __restrict__ cols,
                               const float* __restrict__ vals, int E) {
    int i = blockIdx.x * blockDim.x + threadIdx.x;
    if (i < E) {
        int p = atomicAdd(&g_rowptr2[rows[i]], 1);
        g_epack[p] = make_int2(cols[i], __float_as_int(vals[i]));
    }
}

// ---------------- Tensor-core GEMM via fp16 mma.sync ----------------
// C[M,BN] = A[M,K] * W[BN,K]^T, 2-term fp16 split: D += Ah*Bh + Ah*Bl.
// AHALF: A already fp16 (Ah == A exactly; smem fill is a straight copy).
// K-chunk = 64 -> 128B fp16 rows, SW128 swizzle, double-buffered. fp16 out.
template <int BM, int BN, int WM, int WN, int K, bool AHALF>
__global__ void __launch_bounds__(WM * WN * 32, 2)
mma_gemm_kernel(const void* __restrict__ Av, const float* __restrict__ W,
                __half* __restrict__ C, int M)
{
    constexpr int THREADS = WM * WN * 32;
    constexpr int NCHUNK  = K / 64;
    constexpr int ASZ = BM * 128;
    constexpr int BSZ = BN * 128;
    constexpr int BUF = ASZ + 2 * BSZ;
    constexpr int ALF = BM * 16 / THREADS;
    constexpr int ALH = BM * 8 / THREADS;
    constexpr int BL  = BN * 16 / THREADS;
    constexpr int MT  = BM / WM / 16;
    constexpr int NT  = BN / WN / 8;

    extern __shared__ __align__(1024) char smem[];
    const uint32_t sb = smem_u32(smem);

    const int tid = threadIdx.x;
    const int l   = tid & 31;
    const int w   = tid >> 5;
    const int wmBase = (w % WM) * (BM / WM);
    const int wnBase = (w / WM) * (BN / WN);
    const int m0 = blockIdx.x * BM;

    const float*  Af = (const float*)Av;
    const __half* Ah = (const __half*)Av;

    float acc[MT][NT][4];
    #pragma unroll
    for (int i = 0; i < MT; i++)
        #pragma unroll
        for (int j = 0; j < NT; j++)
            #pragma unroll
            for (int q = 0; q < 4; q++) acc[i][j][q] = 0.f;

    uint2 regAh[AHALF ? 1 : ALF];
    uint4 regAp[AHALF ? ALH : 1];
    uint2 regBh[BL], regBl[BL];

    const int arow = l & 15;
    const int acol = (l & 16) ? 16 : 0;
    const int brow = ((l & 16) ? 8 : 0) + (l & 7);
    const int bcol = (l & 8) ? 16 : 0;

    auto loadChunk = [&](int c) {
        const int k0 = c * 64;
        if constexpr (AHALF) {
            #pragma unroll
            for (int i = 0; i < ALH; i++) {
                int idx = tid + i * THREADS;
                int r = idx >> 3, u = idx & 7;
                int row = m0 + r; if (row >= M) row = M - 1;
                regAp[i] = __ldg((const uint4*)(Ah + (size_t)row * K + k0) + u);
            }
        } else {
            #pragma unroll
            for (int i = 0; i < ALF; i++) {
                int idx = tid + i * THREADS;
                int r = idx >> 4, c4 = (idx & 15) << 2;
                int row = m0 + r; if (row >= M) row = M - 1;
                float4 v = __ldg((const float4*)(Af + (size_t)row * K + k0 + c4));
                regAh[i] = cvt_hi(v);
            }
        }
        #pragma unroll
        for (int i = 0; i < BL; i++) {
            int idx = tid + i * THREADS;
            int r = idx >> 4, c4 = (idx & 15) << 2;
            float4 v = __ldg((const float4*)(W + (size_t)r * K + k0 + c4));
            regBh[i] = cvt_hi(v);
            regBl[i] = cvt_lo(v, regBh[i]);
        }
    };

    auto stsChunk = [&](int b) {
        char* base = smem + b * BUF;
        char* aHi  = base;
        char* bHi  = base + ASZ;
        char* bLo  = bHi + BSZ;
        if constexpr (AHALF) {
            #pragma unroll
            for (int i = 0; i < ALH; i++) {
                int idx = tid + i * THREADS;
                int r = idx >> 3, u = idx & 7;
                *(uint4*)(aHi + sw128((uint32_t)(r * 128 + u * 16))) = regAp[i];
            }
        } else {
            #pragma unroll
            for (int i = 0; i < ALF; i++) {
                int idx = tid + i * THREADS;
                int r = idx >> 4, c4 = (idx & 15) << 2;
                *(uint2*)(aHi + sw128((uint32_t)(r * 128 + c4 * 2))) = regAh[i];
            }
        }
        #pragma unroll
        for (int i = 0; i < BL; i++) {
            int idx = tid + i * THREADS;
            int r = idx >> 4, c4 = (idx & 15) << 2;
            uint32_t off = sw128((uint32_t)(r * 128 + c4 * 2));
            *(uint2*)(bHi + off) = regBh[i];
            *(uint2*)(bLo + off) = regBl[i];
        }
    };

    auto compute = [&](int b) {
        const uint32_t sAhi = sb + b * BUF;
        const uint32_t sBhi = sAhi + ASZ;
        const uint32_t sBlo = sBhi + BSZ;
        #pragma unroll
        for (int kb = 0; kb < 4; kb++) {
            const int kboff = kb * 32;
            uint32_t aH[MT][4];
            #pragma unroll
            for (int mt = 0; mt < MT; mt++) {
                uint32_t rowb = (uint32_t)((wmBase + mt * 16 + arow) * 128);
                ldsm_x4(aH[mt], sAhi + sw128(rowb + kboff + acol));
            }
            uint32_t bH[NT][2], bLo[NT][2];
            #pragma unroll
            for (int nt = 0; nt < NT; nt += 2) {
                uint32_t rowb = (uint32_t)((wnBase + nt * 8 + brow) * 128);
                uint32_t t[4];
                ldsm_x4(t, sBhi + sw128(rowb + kboff + bcol));
                bH[nt][0] = t[0]; bH[nt][1] = t[1];
                bH[nt + 1][0] = t[2]; bH[nt + 1][1] = t[3];
                ldsm_x4(t, sBlo + sw128(rowb + kboff + bcol));
                bLo[nt][0] = t[0]; bLo[nt][1] = t[1];
                bLo[nt + 1][0] = t[2]; bLo[nt + 1][1] = t[3];
            }
            #pragma unroll
            for (int mt = 0; mt < MT; mt++)
                #pragma unroll
                for (int nt = 0; nt < NT; nt++) {
                    mma16816(acc[mt][nt], aH[mt], bH[nt]);
                    mma16816(acc[mt][nt], aH[mt], bLo[nt]);
                }
        }
    };

    loadChunk(0);
    stsChunk(0);
    __syncthreads();

    for (int c = 0; c < NCHUNK; c++) {
        if (c + 1 < NCHUNK) loadChunk(c + 1);
        compute(c & 1);
        if (c + 1 < NCHUNK) {
            __syncthreads();
            stsChunk((c + 1) & 1);
            __syncthreads();
        }
    }

    #pragma unroll
    for (int mt = 0; mt < MT; mt++) {
        int m = m0 + wmBase + mt * 16 + (l >> 2);
        #pragma unroll
        for (int nt = 0; nt < NT; nt++) {
            int nn = wnBase + nt * 8 + ((l & 3) << 1);
            if (m < M)
                *(__half2*)(C + (size_t)m * BN + nn) =
                    __floats2half2_rn(acc[mt][nt][0], acc[mt][nt][1]);
            if (m + 8 < M)
                *(__half2*)(C + (size_t)(m + 8) * BN + nn) =
                    __floats2half2_rn(acc[mt][nt][2], acc[mt][nt][3]);
        }
    }
}

// ---------------- SpMM (CSR, warp per row, fp16 gather, 2x unroll) ---------
// h fp16, accumulate fp32. OUTHALF: store fp16, else fp32.
template <int WIDTH, bool RELU, bool OUTHALF>
__global__ void spmm_kernel(const __half* __restrict__ h,
                            void* __restrict__ outv, int n) {
    int warp = (blockIdx.x * blockDim.x + threadIdx.x) >> 5;
    int lane = threadIdx.x & 31;
    if (warp >= n) return;
    int s = g_rowptr[warp];
    int e = g_rowptr[warp + 1];

    if (WIDTH == 128) {
        float4 acc = make_float4(0.f, 0.f, 0.f, 0.f);
        int i = s;
        for (; i + 2 <= e; i += 2) {
            int2 p0 = g_epack[i];
            int2 p1 = g_epack[i + 1];
            float v0 = __int_as_float(p0.y);
            float v1 = __int_as_float(p1.y);
            uint2 r0 = __ldg((const uint2*)(h + (size_t)p0.x * 128) + lane);
            uint2 r1 = __ldg((const uint2*)(h + (size_t)p1.x * 128) + lane);
            float2 a01 = __half22float2(*(__half2*)&r0.x);
            float2 a23 = __half22float2(*(__half2*)&r0.y);
            float2 b01 = __half22float2(*(__half2*)&r1.x);
            float2 b23 = __half22float2(*(__half2*)&r1.y);
            acc.x += v0 * a01.x; acc.y += v0 * a01.y;
            acc.z += v0 * a23.x; acc.w += v0 * a23.y;
            acc.x += v1 * b01.x; acc.y += v1 * b01.y;
            acc.z += v1 * b23.x; acc.w += v1 * b23.y;
        }
        if (i < e) {
            int2 p = g_epack[i];
            float v = __int_as_float(p.y);
            uint2 r0 = __ldg((const uint2*)(h + (size_t)p.x * 128) + lane);
            float2 a01 = __half22float2(*(__half2*)&r0.x);
            float2 a23 = __half22float2(*(__half2*)&r0.y);
            acc.x += v * a01.x; acc.y += v * a01.y;
            acc.z += v * a23.x; acc.w += v * a23.y;
        }
        if (RELU) {
            acc.x = fmaxf(acc.x, 0.f); acc.y = fmaxf(acc.y, 0.f);
            acc.z = fmaxf(acc.z, 0.f); acc.w = fmaxf(acc.w, 0.f);
        }
        if constexpr (OUTHALF) {
            __half2 o01 = __floats2half2_rn(acc.x, acc.y);
            __half2 o23 = __floats2half2_rn(acc.z, acc.w);
            ((uint2*)((__half*)outv + (size_t)warp * 128))[lane] =
                make_uint2(*(uint32_t*)&o01, *(uint32_t*)&o23);
        } else {
            ((float4*)((float*)outv + (size_t)warp * 128))[lane] = acc;
        }
    } else {  // WIDTH == 64
        float2 acc = make_float2(0.f, 0.f);
        int i = s;
        for (; i + 2 <= e; i += 2) {
            int2 p0 = g_epack[i];
            int2 p1 = g_epack[i + 1];
            float v0 = __int_as_float(p0.y);
            float v1 = __int_as_float(p1.y);
            uint32_t r0 = __ldg((const uint32_t*)(h + (size_t)p0.x * 64) + lane);
            uint32_t r1 = __ldg((const uint32_t*)(h + (size_t)p1.x * 64) + lane);
            float2 a = __half22float2(*(__half2*)&r0);
            float2 b = __half22float2(*(__half2*)&r1);
            acc.x += v0 * a.x; acc.y += v0 * a.y;
            acc.x += v1 * b.x; acc.y += v1 * b.y;
        }
        if (i < e) {
            int2 p = g_epack[i];
            float v = __int_as_float(p.y);
            uint32_t r0 = __ldg((const uint32_t*)(h + (size_t)p.x * 64) + lane);
            float2 a = __half22float2(*(__half2*)&r0);
            acc.x += v * a.x; acc.y += v * a.y;
        }
        if (RELU) { acc.x = fmaxf(acc.x, 0.f); acc.y = fmaxf(acc.y, 0.f); }
        ((float2*)((float*)outv + (size_t)warp * 64))[lane] = acc;
    }
}

// ---------------- Launcher ----------------
extern "C" void kernel_launch(void* const* d_in, const int* in_sizes, int n_in,
                              void* d_out, int out_size) {
    const float* x    = (const float*)d_in[0];
    const int*   rows = (const int*)  d_in[1];
    const int*   cols = (const int*)  d_in[2];
    const float* vals = (const float*)d_in[3];
    const float* W0   = (const float*)d_in[4];
    const float* W1   = (const float*)d_in[5];
    const float* W2   = (const float*)d_in[6];
    float* out = (float*)d_out;

    int n = in_sizes[0] / DIM_IN;   // 100000
    int E = in_sizes[1];            // 1600000
    int nb = (n + SCAN_BLK - 1) / SCAN_BLK;

    float* bufA; float* bufB;
    cudaGetSymbolAddress((void**)&bufA, g_bufA);
    cudaGetSymbolAddress((void**)&bufB, g_bufB);
    __half* bufAh = (__half*)bufA;
    __half* bufBh = (__half*)bufB;

    const int smemG0 = 2 * 48 * 1024;
    const int smemG2 = 2 * 32 * 1024;
    cudaFuncSetAttribute(mma_gemm_kernel<128, 128, 2, 4, 512, false>,
                         cudaFuncAttributeMaxDynamicSharedMemorySize, smemG0);
    cudaFuncSetAttribute(mma_gemm_kernel<128, 128, 2, 4, 128, true>,
                         cudaFuncAttributeMaxDynamicSharedMemorySize, smemG0);
    cudaFuncSetAttribute(mma_gemm_kernel<128, 64, 4, 2, 128, true>,
                         cudaFuncAttributeMaxDynamicSharedMemorySize, smemG2);

    // ---- CSR build (multi-block scan, single-atomic scatter) ----
    zero_deg_kernel<<<(n + 255) / 256, 256>>>(n);
    hist_kernel<<<(E + 255) / 256, 256>>>(rows, E);
    scan_blocks_kernel<<<nb, SCAN_BLK>>>(n);
    scan_partials_kernel<<<1, 128>>>(nb, n);
    scan_add_kernel<<<nb, SCAN_BLK>>>(n);
    scatter_kernel<<<(E + 255) / 256, 256>>>(rows, cols, vals, E);

    int gemmGrid = (n + 127) / 128;
    int spmmGrid = (n + 7) / 8;

    // layer 0: x(fp32) @ W0^T -> fp16; spmm fp16->fp16 + relu
    mma_gemm_kernel<128, 128, 2, 4, 512, false><<<gemmGrid, 256, smemG0>>>(x, W0, bufAh, n);
    spmm_kernel<128, true, true><<<spmmGrid, 256>>>(bufAh, bufBh, n);

    // layer 1: h(fp16) @ W1^T -> fp16; spmm fp16->fp16 + relu
    mma_gemm_kernel<128, 128, 2, 4, 128, true><<<gemmGrid, 256, smemG0>>>(bufBh, W1, bufAh, n);
    spmm_kernel<128, true, true><<<spmmGrid, 256>>>(bufAh, bufBh, n);

    // layer 2: h(fp16) @ W2^T -> fp16; spmm fp16->fp32 (no relu)
    mma_gemm_kernel<128, 64, 4, 2, 128, true><<<gemmGrid, 256, smemG2>>>(bufBh, W2, bufAh, n);
    spmm_kernel<64, false, false><<<spmmGrid, 256>>>(bufAh, out, n);
}